// round 10
// baseline (speedup 1.0000x reference)
#include <cuda_runtime.h>
#include <cstdint>
#include <math.h>

#define BB 8
#define SS 4096
#define DD 1024
#define NN 64
#define SHIFT 2048
#define NCH 128
#define CHL 32
#define TILE_C 32
#define XPITCH 68

// ---------------- scratch (device globals) ----------------
__device__ float g_wT[DD * 128];            // [d][o]: o=2n -> lnw*kw, o=2n+1 -> lnw*vw
__device__ float g_wsum[128];
__device__ float g_lbsum[128];
__device__ float g_gate[DD];
__device__ float g_w[NN];                   // exp(time_decay)
__device__ float g_exptf[NN];               // exp(time_first)
__device__ float4 g_owQ[16 * DD];           // [n4][d] = ow[d][4n4..4n4+3]
__device__ float g_wkv[BB * SS * NN];
__device__ float g_chunk[BB * NCH * NN];
__device__ float g_carry[BB * NCH * NN];

// ---------------- packed fp32x2 FMA (sm_103a FFMA2) ----------------
__device__ __forceinline__ float2 ffma2(float2 a, float2 b, float2 c) {
    float2 d;
    asm("fma.rn.f32x2 %0, %1, %2, %3;"
        : "=l"(*reinterpret_cast<unsigned long long*>(&d))
        : "l"(*reinterpret_cast<unsigned long long*>(&a)),
          "l"(*reinterpret_cast<unsigned long long*>(&b)),
          "l"(*reinterpret_cast<unsigned long long*>(&c)));
    return d;
}

// ---------------- prep kernels ----------------
__global__ void prep_a(const float* __restrict__ kw, const float* __restrict__ vw,
                       const float* __restrict__ lnw, const float* __restrict__ tsg,
                       const float* __restrict__ td, const float* __restrict__ tf) {
    int idx = blockIdx.x * 256 + threadIdx.x;   // 0..131071
    int d = idx >> 7;
    int o = idx & 127;
    int n = o >> 1;
    const float* src = (o & 1) ? vw : kw;
    g_wT[idx] = lnw[d] * src[n * DD + d];
    if (o == 0) g_gate[d] = 1.f / (1.f + expf(-tsg[d]));
    if (idx < NN) g_w[idx] = expf(td[idx]);
    else if (idx < 2 * NN) g_exptf[idx - NN] = expf(tf[idx - NN]);
}

__global__ void prep_ow(const float* __restrict__ ow) {
    int idx = blockIdx.x * 256 + threadIdx.x;   // 0..16383
    int d = idx & (DD - 1);
    int n4 = idx >> 10;
    g_owQ[idx] = *reinterpret_cast<const float4*>(&ow[d * NN + 4 * n4]);
}

__global__ void prep_b(const float* __restrict__ kw, const float* __restrict__ vw,
                       const float* __restrict__ lnb) {
    __shared__ float red[2][8];
    int o = blockIdx.x;
    int n = o >> 1;
    const float* src = (o & 1) ? vw : kw;
    int tid = threadIdx.x;
    float ws = 0.f, lb = 0.f;
    for (int d = tid; d < DD; d += 256) {
        ws += g_wT[d * 128 + o];
        lb += lnb[d] * src[n * DD + d];
    }
#pragma unroll
    for (int off = 16; off; off >>= 1) {
        ws += __shfl_xor_sync(0xffffffffu, ws, off);
        lb += __shfl_xor_sync(0xffffffffu, lb, off);
    }
    if ((tid & 31) == 0) { red[0][tid >> 5] = ws; red[1][tid >> 5] = lb; }
    __syncthreads();
    if (tid == 0) {
        float a = 0.f, c = 0.f;
#pragma unroll
        for (int i = 0; i < 8; i++) { a += red[0][i]; c += red[1][i]; }
        g_wsum[o] = a;
        g_lbsum[o] = c;
    }
}

// ---------------- kernel A: resident-weight quarter GEMM ----------------
// grid: BB * 32 * 4 = 1024 blocks, 256 threads.
// Block = (b, 64-row mirror pair-tile t0/t0+2048, column quarter q).
// Weights quarter (1024 x 32) resident in smem; x streamed in 64-d chunks,
// double-buffered, prefetched in registers across the GEMM.
// smem floats: wq[32768] | xs0[128*68] xs1[128*68] | gate[1024] | mu[128] inv[128]
__global__ void __launch_bounds__(256)
kernelA(const float* __restrict__ x) {
    extern __shared__ float sm[];
    float* wq = sm;                                  // 32768
    float* xsb[2] = { sm + 32768, sm + 32768 + 128 * XPITCH };
    float* gate_s = sm + 32768 + 2 * 128 * XPITCH;   // 1024
    float* mu_s   = gate_s + 1024;                   // 128
    float* inv_s  = mu_s + 128;                      // 128

    int b   = blockIdx.x >> 7;
    int rem = blockIdx.x & 127;
    int tpos = rem >> 2;               // 0..31
    int q    = rem & 3;                // column quarter
    int t0   = tpos * 64;
    int tid = threadIdx.x;
    int lane = tid & 31;
    int warp = tid >> 5;
    int cg = lane & 7;                 // col group (4 cols)
    int rg = lane >> 3;                // row group within 4

    // ---- stage weight quarter + gate ----
#pragma unroll 4
    for (int u = 0; u < 32; u++) {
        int v = u * 256 + tid;         // 0..8191
        int d = v >> 3, j4 = v & 7;
        *reinterpret_cast<float4*>(&wq[d * 32 + j4 * 4]) =
            *reinterpret_cast<const float4*>(&g_wT[d * 128 + q * 32 + j4 * 4]);
    }
    reinterpret_cast<float4*>(gate_s)[tid] = reinterpret_cast<const float4*>(g_gate)[tid];

    // ---- per-thread x staging pointers: srow = e*16 + (tid>>4), c4 = tid&15 ----
    const float* xtp[4];
    const float* xcp[4];
#pragma unroll
    for (int e = 0; e < 4; e++) {
        int srow = e * 16 + (tid >> 4);
        xtp[e] = x + ((size_t)(b * SS) + t0 + srow) * DD + (tid & 15) * 4;
        xcp[e] = x + ((size_t)(b * SS) + t0 + SHIFT + srow) * DD + (tid & 15) * 4;
    }

    float st_sum[8], st_sq[8];
#pragma unroll
    for (int e = 0; e < 8; e++) { st_sum[e] = 0.f; st_sq[e] = 0.f; }

    float2 acc[4][2];
#pragma unroll
    for (int i = 0; i < 4; i++) { acc[i][0] = make_float2(0.f, 0.f); acc[i][1] = make_float2(0.f, 0.f); }

    float4 pxt[4], pxc[4];
    // prologue: LDG chunk 0
#pragma unroll
    for (int e = 0; e < 4; e++) { pxt[e] = *reinterpret_cast<const float4*>(xtp[e]);
                                  pxc[e] = *reinterpret_cast<const float4*>(xcp[e]); }
    __syncthreads();   // weights + gate staged

    // blend chunk 0 into buffer 0
    {
        int c4 = tid & 15;
        float4 g4 = *reinterpret_cast<const float4*>(&gate_s[c4 * 4]);
#pragma unroll
        for (int e = 0; e < 4; e++) {
            int srow = e * 16 + (tid >> 4);
            float4 s0, s1;
            s0.x = pxt[e].x + g4.x * (pxc[e].x - pxt[e].x);
            s0.y = pxt[e].y + g4.y * (pxc[e].y - pxt[e].y);
            s0.z = pxt[e].z + g4.z * (pxc[e].z - pxt[e].z);
            s0.w = pxt[e].w + g4.w * (pxc[e].w - pxt[e].w);
            s1.x = pxc[e].x + g4.x * (pxt[e].x - pxc[e].x);
            s1.y = pxc[e].y + g4.y * (pxt[e].y - pxc[e].y);
            s1.z = pxc[e].z + g4.z * (pxt[e].z - pxc[e].z);
            s1.w = pxc[e].w + g4.w * (pxt[e].w - pxc[e].w);
            st_sum[2 * e]     += s0.x + s0.y + s0.z + s0.w;
            st_sq[2 * e]      += s0.x * s0.x + s0.y * s0.y + s0.z * s0.z + s0.w * s0.w;
            st_sum[2 * e + 1] += s1.x + s1.y + s1.z + s1.w;
            st_sq[2 * e + 1]  += s1.x * s1.x + s1.y * s1.y + s1.z * s1.z + s1.w * s1.w;
            *reinterpret_cast<float4*>(&xsb[0][srow * XPITCH + c4 * 4]) = s0;
            *reinterpret_cast<float4*>(&xsb[0][(srow + 64) * XPITCH + c4 * 4]) = s1;
        }
    }
    __syncthreads();

#pragma unroll 1
    for (int ch = 0; ch < 16; ch++) {
        int buf = ch & 1;
        if (ch < 15) {
            int off = (ch + 1) * 64;
#pragma unroll
            for (int e = 0; e < 4; e++) {
                pxt[e] = *reinterpret_cast<const float4*>(xtp[e] + off);
                pxc[e] = *reinterpret_cast<const float4*>(xcp[e] + off);
            }
        }

        // GEMM: warp owns rows warp*16 + 4i + rg, lane cols cg*4..+3
        const float* aB = &xsb[buf][(warp * 16) * XPITCH];
        const float* wB = &wq[ch * 64 * 32];
#pragma unroll 4
        for (int dl4 = 0; dl4 < 16; dl4++) {
            float4 wv[4];
#pragma unroll
            for (int k = 0; k < 4; k++)
                wv[k] = *reinterpret_cast<const float4*>(&wB[(dl4 * 4 + k) * 32 + cg * 4]);
            float4 av[4];
#pragma unroll
            for (int i = 0; i < 4; i++)
                av[i] = *reinterpret_cast<const float4*>(&aB[(4 * i + rg) * XPITCH + dl4 * 4]);
#pragma unroll
            for (int i = 0; i < 4; i++) {
                float2 p;
                p = make_float2(av[i].x, av[i].x);
                acc[i][0] = ffma2(p, make_float2(wv[0].x, wv[0].y), acc[i][0]);
                acc[i][1] = ffma2(p, make_float2(wv[0].z, wv[0].w), acc[i][1]);
                p = make_float2(av[i].y, av[i].y);
                acc[i][0] = ffma2(p, make_float2(wv[1].x, wv[1].y), acc[i][0]);
                acc[i][1] = ffma2(p, make_float2(wv[1].z, wv[1].w), acc[i][1]);
                p = make_float2(av[i].z, av[i].z);
                acc[i][0] = ffma2(p, make_float2(wv[2].x, wv[2].y), acc[i][0]);
                acc[i][1] = ffma2(p, make_float2(wv[2].z, wv[2].w), acc[i][1]);
                p = make_float2(av[i].w, av[i].w);
                acc[i][0] = ffma2(p, make_float2(wv[3].x, wv[3].y), acc[i][0]);
                acc[i][1] = ffma2(p, make_float2(wv[3].z, wv[3].w), acc[i][1]);
            }
        }

        // blend prefetched chunk into the other buffer
        if (ch < 15) {
            int c4 = tid & 15;
            float4 g4 = *reinterpret_cast<const float4*>(&gate_s[(ch + 1) * 64 + c4 * 4]);
            float* xd = xsb[buf ^ 1];
#pragma unroll
            for (int e = 0; e < 4; e++) {
                int srow = e * 16 + (tid >> 4);
                float4 s0, s1;
                s0.x = pxt[e].x + g4.x * (pxc[e].x - pxt[e].x);
                s0.y = pxt[e].y + g4.y * (pxc[e].y - pxt[e].y);
                s0.z = pxt[e].z + g4.z * (pxc[e].z - pxt[e].z);
                s0.w = pxt[e].w + g4.w * (pxc[e].w - pxt[e].w);
                s1.x = pxc[e].x + g4.x * (pxt[e].x - pxc[e].x);
                s1.y = pxc[e].y + g4.y * (pxt[e].y - pxc[e].y);
                s1.z = pxc[e].z + g4.z * (pxt[e].z - pxc[e].z);
                s1.w = pxc[e].w + g4.w * (pxt[e].w - pxc[e].w);
                st_sum[2 * e]     += s0.x + s0.y + s0.z + s0.w;
                st_sq[2 * e]      += s0.x * s0.x + s0.y * s0.y + s0.z * s0.z + s0.w * s0.w;
                st_sum[2 * e + 1] += s1.x + s1.y + s1.z + s1.w;
                st_sq[2 * e + 1]  += s1.x * s1.x + s1.y * s1.y + s1.z * s1.z + s1.w * s1.w;
                *reinterpret_cast<float4*>(&xd[srow * XPITCH + c4 * 4]) = s0;
                *reinterpret_cast<float4*>(&xd[(srow + 64) * XPITCH + c4 * 4]) = s1;
            }
        }
        __syncthreads();
    }

    // ---- LN stats finalize (16-consecutive-tid groups share a row) ----
#pragma unroll
    for (int e = 0; e < 4; e++) {
#pragma unroll
        for (int h = 0; h < 2; h++) {
            float s = st_sum[2 * e + h], qq = st_sq[2 * e + h];
#pragma unroll
            for (int off = 8; off; off >>= 1) {
                s  += __shfl_xor_sync(0xffffffffu, s, off);
                qq += __shfl_xor_sync(0xffffffffu, qq, off);
            }
            if ((lane & 15) == 0) {
                int row = e * 16 + (tid >> 4) + h * 64;
                float mu = s * (1.f / DD);
                float var = qq * (1.f / DD) - mu * mu;
                mu_s[row] = mu;
                inv_s[row] = rsqrtf(var + 1e-5f);
            }
        }
    }
    __syncthreads();

    // ---- epilogue: LN fold + wkv (quarter columns) ----
    float* wkv_s = wq;                      // 128 x 16 overlay
    int n0 = q * 16 + cg * 2;
    int n1 = n0 + 1;
#pragma unroll
    for (int i = 0; i < 4; i++) {
        int r = warp * 16 + 4 * i + rg;
        int t = t0 + ((r < 64) ? r : (SHIFT + r - 64));
        float mu = mu_s[r], inv = inv_s[r];
        float k0 = inv * (acc[i][0].x - mu * g_wsum[2 * n0])     + g_lbsum[2 * n0];
        float v0 = inv * (acc[i][0].y - mu * g_wsum[2 * n0 + 1]) + g_lbsum[2 * n0 + 1];
        float wk0 = expf(-g_exptf[n0] * k0) * v0;
        float k1 = inv * (acc[i][1].x - mu * g_wsum[2 * n1])     + g_lbsum[2 * n1];
        float v1 = inv * (acc[i][1].y - mu * g_wsum[2 * n1 + 1]) + g_lbsum[2 * n1 + 1];
        float wk1 = expf(-g_exptf[n1] * k1) * v1;
        float2 wv = make_float2(wk0, wk1);
        *reinterpret_cast<float2*>(&g_wkv[((size_t)(b * SS) + t) * NN + n0]) = wv;
        *reinterpret_cast<float2*>(&wkv_s[r * 16 + cg * 2]) = wv;
    }
    __syncthreads();
    if (tid < 64) {
        int sub = tid >> 4;                 // 0..3
        int nl = tid & 15;
        int n = q * 16 + nl;
        int cb = (sub < 2) ? (tpos * 2 + sub) : (tpos * 2 + 64 + sub - 2);
        float w = g_w[n];
        float a = 0.f;
#pragma unroll
        for (int r2 = 0; r2 < 32; r2++) a = a * w + wkv_s[(sub * 32 + r2) * 16 + nl];
        g_chunk[((size_t)b * NCH + cb) * NN + n] = a;
    }
}

// ---------------- carry prefix over chunks ----------------
__global__ void scan_carry(const float* __restrict__ td, float* __restrict__ lastout,
                           int write_last) {
    int tid = threadIdx.x;                  // 512 threads
    int n = tid & (NN - 1);
    int b = tid >> 6;
    float wL = expf((float)CHL * td[n]);
    float carry = 0.f;
    for (int c0 = 0; c0 < NCH; c0 += 8) {
        float v[8];
#pragma unroll
        for (int i = 0; i < 8; i++) v[i] = g_chunk[((size_t)b * NCH + c0 + i) * NN + n];
#pragma unroll
        for (int i = 0; i < 8; i++) {
            g_carry[((size_t)b * NCH + c0 + i) * NN + n] = carry;
            carry = carry * wL + v[i];
        }
    }
    if (write_last) lastout[b * NN + n] = carry;
}

// ---------------- kernel C: fused scan + output projection ----------------
#define SPITCH 36
__global__ void __launch_bounds__(1024, 1)
kernelC(float* __restrict__ out) {
    __shared__ float wk[TILE_C * NN];       // 2048
    __shared__ float sT[NN * SPITCH];       // 2304

    int b = blockIdx.x >> 7;
    int c = blockIdx.x & 127;
    int t0 = c * TILE_C;
    int tid = threadIdx.x;
    int wg = tid >> 9;
    int dtid = tid & 511;

    if (tid < 512)
        reinterpret_cast<float4*>(wk)[tid] =
            reinterpret_cast<const float4*>(&g_wkv[((size_t)(b * SS) + t0) * NN])[tid];
    __syncthreads();

    if (tid < NN) {
        int n = tid;
        float w = g_w[n];
        float st = g_carry[((size_t)b * NCH + c) * NN + n];
#pragma unroll
        for (int r = 0; r < TILE_C; r++) {
            st = st * w + wk[r * NN + n];
            sT[n * SPITCH + r] = st;
        }
    }
    __syncthreads();

    float2 acc[8][2];
#pragma unroll
    for (int p = 0; p < 8; p++) { acc[p][0] = make_float2(0.f, 0.f); acc[p][1] = make_float2(0.f, 0.f); }

    const float* sBase = &sT[wg * 16];
#pragma unroll 2
    for (int n4 = 0; n4 < 16; n4++) {
        float4 wA = __ldg(&g_owQ[n4 * 1024 + dtid]);
        float4 wB = __ldg(&g_owQ[n4 * 1024 + 512 + dtid]);
#pragma unroll
        for (int j = 0; j < 4; j++) {
            int n = 4 * n4 + j;
            float wa = (j == 0) ? wA.x : (j == 1) ? wA.y : (j == 2) ? wA.z : wA.w;
            float wb2v = (j == 0) ? wB.x : (j == 1) ? wB.y : (j == 2) ? wB.z : wB.w;
            float2 wa2 = make_float2(wa, wa);
            float2 wb2 = make_float2(wb2v, wb2v);
            const float* sb = sBase + n * SPITCH;
#pragma unroll
            for (int qq = 0; qq < 4; qq++) {
                float4 s4 = *reinterpret_cast<const float4*>(sb + 4 * qq);
                float2 slo = make_float2(s4.x, s4.y);
                float2 shi = make_float2(s4.z, s4.w);
                acc[2 * qq][0]     = ffma2(slo, wa2, acc[2 * qq][0]);
                acc[2 * qq][1]     = ffma2(slo, wb2, acc[2 * qq][1]);
                acc[2 * qq + 1][0] = ffma2(shi, wa2, acc[2 * qq + 1][0]);
                acc[2 * qq + 1][1] = ffma2(shi, wb2, acc[2 * qq + 1][1]);
            }
        }
    }

    float* ob = out + ((size_t)(b * SS) + t0 + wg * 16) * DD;
#pragma unroll
    for (int p = 0; p < 8; p++) {
        ob[(size_t)(2 * p) * DD + dtid]           = acc[p][0].x;
        ob[(size_t)(2 * p + 1) * DD + dtid]       = acc[p][0].y;
        ob[(size_t)(2 * p) * DD + 512 + dtid]     = acc[p][1].x;
        ob[(size_t)(2 * p + 1) * DD + 512 + dtid] = acc[p][1].y;
    }
}

// ---------------- launch ----------------
extern "C" void kernel_launch(void* const* d_in, const int* in_sizes, int n_in,
                              void* d_out, int out_size) {
    const float* x   = (const float*)d_in[0];
    const float* td  = (const float*)d_in[1];
    const float* tf  = (const float*)d_in[2];
    const float* kw  = (const float*)d_in[3];
    const float* vw  = (const float*)d_in[4];
    const float* ow  = (const float*)d_in[5];
    const float* tsg = (const float*)d_in[6];
    const float* lnw = (const float*)d_in[7];
    const float* lnb = (const float*)d_in[8];
    float* out = (float*)d_out;

    const int SMEM_A = (32768 + 2 * 128 * XPITCH + 1024 + 256) * (int)sizeof(float);  // 205824 B
    cudaFuncSetAttribute(kernelA, cudaFuncAttributeMaxDynamicSharedMemorySize, SMEM_A);

    prep_a<<<(DD * 128) / 256, 256>>>(kw, vw, lnw, tsg, td, tf);
    prep_ow<<<64, 256>>>(ow);
    prep_b<<<128, 256>>>(kw, vw, lnb);
    kernelA<<<BB * 32 * 4, 256, SMEM_A>>>(x);
    int write_last = (out_size >= BB * SS * DD + BB * NN) ? 1 : 0;
    scan_carry<<<1, 512>>>(td, out + (size_t)BB * SS * DD, write_last);
    kernelC<<<BB * (SS / TILE_C), 1024>>>(out);
}

// round 12
// speedup vs baseline: 1.7209x; 1.7209x over previous
#include <cuda_runtime.h>
#include <cuda_bf16.h>
#include <cstdint>
#include <math.h>

#define BB 8
#define SS 4096
#define DD 1024
#define NN 64
#define SHIFT 2048
#define NCH 128
#define CHL 32
#define TILE_C 32

// ---------------- scratch (device globals) ----------------
__device__ float g_wT[DD * 128];            // [d][o]: o=2n -> lnw*kw, o=2n+1 -> lnw*vw
__device__ float g_wsum[128];
__device__ float g_lbsum[128];
__device__ float g_gate[DD];
__device__ float g_w[NN];                   // exp(time_decay)
__device__ float g_exptf[NN];               // exp(time_first)
__device__ float4 g_owQ[16 * DD];           // [n4][d] = ow[d][4n4..4n4+3]
__device__ uint4 g_bfrag[16 * 2048];        // frag-major bf16 weights: [ch][s][n8][lane] = (b0h,b1h,b0l,b1l)
__device__ float g_wkv[BB * SS * NN];
__device__ float g_chunk[BB * NCH * NN];
__device__ float g_carry[BB * NCH * NN];

// ---------------- packed fp32x2 FMA ----------------
__device__ __forceinline__ float2 ffma2(float2 a, float2 b, float2 c) {
    float2 d;
    asm("fma.rn.f32x2 %0, %1, %2, %3;"
        : "=l"(*reinterpret_cast<unsigned long long*>(&d))
        : "l"(*reinterpret_cast<unsigned long long*>(&a)),
          "l"(*reinterpret_cast<unsigned long long*>(&b)),
          "l"(*reinterpret_cast<unsigned long long*>(&c)));
    return d;
}

// ---------------- HMMA helpers (sm_80+ baseline; no 'a' features) ----------------
__device__ __forceinline__ void mma_bf16(float* c, const unsigned* a, unsigned b0, unsigned b1) {
    asm volatile("mma.sync.aligned.m16n8k16.row.col.f32.bf16.bf16.f32 "
                 "{%0,%1,%2,%3}, {%4,%5,%6,%7}, {%8,%9}, {%0,%1,%2,%3};"
                 : "+f"(c[0]), "+f"(c[1]), "+f"(c[2]), "+f"(c[3])
                 : "r"(a[0]), "r"(a[1]), "r"(a[2]), "r"(a[3]), "r"(b0), "r"(b1));
}
__device__ __forceinline__ void ldm4(unsigned* r, unsigned addr) {
    asm volatile("ldmatrix.sync.aligned.m8n8.x4.shared.b16 {%0,%1,%2,%3}, [%4];"
                 : "=r"(r[0]), "=r"(r[1]), "=r"(r[2]), "=r"(r[3]) : "r"(addr));
}
__device__ __forceinline__ unsigned packbf(float a, float b) {
    __nv_bfloat162 t = __floats2bfloat162_rn(a, b);
    return *reinterpret_cast<unsigned*>(&t);
}

// ---------------- prep kernels ----------------
__global__ void prep_a(const float* __restrict__ kw, const float* __restrict__ vw,
                       const float* __restrict__ lnw, const float* __restrict__ tsg,
                       const float* __restrict__ td, const float* __restrict__ tf) {
    int idx = blockIdx.x * 256 + threadIdx.x;
    int d = idx >> 7;
    int o = idx & 127;
    int n = o >> 1;
    const float* src = (o & 1) ? vw : kw;
    g_wT[idx] = lnw[d] * src[n * DD + d];
    if (o == 0) g_gate[d] = 1.f / (1.f + expf(-tsg[d]));
    if (idx < NN) g_w[idx] = expf(td[idx]);
    else if (idx < 2 * NN) g_exptf[idx - NN] = expf(tf[idx - NN]);
}

// fragment-major bf16 hi/lo weight pack for mma.sync m16n8k16 (B col-major frag)
__global__ void prep_bfrag() {
    int idx = blockIdx.x * 256 + threadIdx.x;   // 0..32767
    int lane = idx & 31;
    int n8 = (idx >> 5) & 15;
    int s = (idx >> 9) & 3;
    int ch = idx >> 11;
    int o = n8 * 8 + (lane >> 2);
    int kb = ch * 64 + s * 16 + (lane & 3) * 2;
    float w0 = g_wT[(size_t)kb * 128 + o];
    float w1 = g_wT[(size_t)(kb + 1) * 128 + o];
    float w8 = g_wT[(size_t)(kb + 8) * 128 + o];
    float w9 = g_wT[(size_t)(kb + 9) * 128 + o];
    float h0 = __bfloat162float(__float2bfloat16_rn(w0));
    float h1 = __bfloat162float(__float2bfloat16_rn(w1));
    float h8 = __bfloat162float(__float2bfloat16_rn(w8));
    float h9 = __bfloat162float(__float2bfloat16_rn(w9));
    g_bfrag[idx] = make_uint4(packbf(h0, h1), packbf(h8, h9),
                              packbf(w0 - h0, w1 - h1), packbf(w8 - h8, w9 - h9));
}

__global__ void prep_ow(const float* __restrict__ ow) {
    int idx = blockIdx.x * 256 + threadIdx.x;
    int d = idx & (DD - 1);
    int n4 = idx >> 10;
    g_owQ[idx] = *reinterpret_cast<const float4*>(&ow[d * NN + 4 * n4]);
}

__global__ void prep_b(const float* __restrict__ kw, const float* __restrict__ vw,
                       const float* __restrict__ lnb) {
    __shared__ float red[2][8];
    int o = blockIdx.x;
    int n = o >> 1;
    const float* src = (o & 1) ? vw : kw;
    int tid = threadIdx.x;
    float ws = 0.f, lb = 0.f;
    for (int d = tid; d < DD; d += 256) {
        ws += g_wT[d * 128 + o];
        lb += lnb[d] * src[n * DD + d];
    }
#pragma unroll
    for (int off = 16; off; off >>= 1) {
        ws += __shfl_xor_sync(0xffffffffu, ws, off);
        lb += __shfl_xor_sync(0xffffffffu, lb, off);
    }
    if ((tid & 31) == 0) { red[0][tid >> 5] = ws; red[1][tid >> 5] = lb; }
    __syncthreads();
    if (tid == 0) {
        float a = 0.f, c = 0.f;
#pragma unroll
        for (int i = 0; i < 8; i++) { a += red[0][i]; c += red[1][i]; }
        g_wsum[o] = a;
        g_lbsum[o] = c;
    }
}

// ---------------- kernel A: HMMA bf16-split KV projection ----------------
// grid 256 (8 b x 32 tiles of 128 rows), 256 threads, occ 2.
// smem bytes: Ah 0..18432 | Al 18432..36864 | Bfrags 36864..69632 |
//             mu 69632 | inv 70144 | wsum 70656 | lbsum 71168 | etf 71680 | end 71936
#define SM_AH 0
#define SM_AL 18432
#define SM_BS 36864
#define SM_MU 69632
#define SM_INV 70144
#define SM_WS 70656
#define SM_LB 71168
#define SM_ETF 71680
#define SMEM_A_BYTES 71936

__global__ void __launch_bounds__(256, 2)
kernelA(const float* __restrict__ x) {
    extern __shared__ char smc[];
    unsigned sbase = (unsigned)__cvta_generic_to_shared(smc);

    int b = blockIdx.x >> 5;
    int tp = blockIdx.x & 31;
    int t0 = tp * 128;
    int tid = threadIdx.x;
    int lane = tid & 31;
    int warp = tid >> 5;
    int row = tid >> 1;                 // staging row 0..127
    int khalf = (tid & 1) * 32;         // float offset within 64-d chunk

    float* mu_s  = reinterpret_cast<float*>(smc + SM_MU);
    float* inv_s = reinterpret_cast<float*>(smc + SM_INV);
    float* ws_s  = reinterpret_cast<float*>(smc + SM_WS);
    float* lb_s  = reinterpret_cast<float*>(smc + SM_LB);
    float* etf_s = reinterpret_cast<float*>(smc + SM_ETF);
    if (tid < 128) {
        ws_s[tid] = g_wsum[tid];
        lb_s[tid] = g_lbsum[tid];
        if (tid < 64) etf_s[tid] = g_exptf[tid];
    }

    const float4* xt4 = reinterpret_cast<const float4*>(x + ((size_t)(b * SS) + t0 + row) * DD);
    const float4* xc4 = reinterpret_cast<const float4*>(x + ((size_t)(b * SS) + ((t0 + row) ^ SHIFT)) * DD);
    const float4* g4 = reinterpret_cast<const float4*>(g_gate);

    float ssum = 0.f, ssq = 0.f;
    float acc[16][4];
#pragma unroll
    for (int j = 0; j < 16; j++)
#pragma unroll
        for (int c = 0; c < 4; c++) acc[j][c] = 0.f;

    char* ah = smc + SM_AH;
    char* al = smc + SM_AL;
    const uint4* bsm = reinterpret_cast<const uint4*>(smc + SM_BS);
    int R0 = warp * 16;

#pragma unroll 1
    for (int ch = 0; ch < 16; ch++) {
        __syncthreads();   // previous compute done; safe to overwrite tiles
        // ---- stage A: blend + stats + bf16 split ----
#pragma unroll
        for (int i = 0; i < 8; i++) {
            int f4i = ch * 16 + (tid & 1) * 8 + i;
            float4 xv = xt4[f4i];
            float4 xc = xc4[f4i];
            float4 g = __ldg(&g4[f4i]);
            float s0 = xv.x + g.x * (xc.x - xv.x);
            float s1 = xv.y + g.y * (xc.y - xv.y);
            float s2 = xv.z + g.z * (xc.z - xv.z);
            float s3 = xv.w + g.w * (xc.w - xv.w);
            ssum += s0 + s1 + s2 + s3;
            ssq  += s0 * s0 + s1 * s1 + s2 * s2 + s3 * s3;
            float h0 = __bfloat162float(__float2bfloat16_rn(s0));
            float h1 = __bfloat162float(__float2bfloat16_rn(s1));
            float h2 = __bfloat162float(__float2bfloat16_rn(s2));
            float h3 = __bfloat162float(__float2bfloat16_rn(s3));
            int klocal = khalf + i * 4;
            *reinterpret_cast<uint2*>(ah + row * 144 + klocal * 2) =
                make_uint2(packbf(h0, h1), packbf(h2, h3));
            *reinterpret_cast<uint2*>(al + row * 144 + klocal * 2) =
                make_uint2(packbf(s0 - h0, s1 - h1), packbf(s2 - h2, s3 - h3));
        }
        // ---- stage B fragments (linear 32 KB copy) ----
        {
            const uint4* bsrc = &g_bfrag[ch * 2048];
            uint4* bdst = reinterpret_cast<uint4*>(smc + SM_BS);
#pragma unroll
            for (int q = 0; q < 8; q++) bdst[q * 256 + tid] = bsrc[q * 256 + tid];
        }
        __syncthreads();

        // ---- compute: 4 k16 steps x 16 n8 tiles x 3 split-MMAs ----
#pragma unroll
        for (int k16 = 0; k16 < 4; k16++) {
            unsigned aoff = (unsigned)((R0 + (lane & 15)) * 144 + (k16 * 16 + ((lane & 16) ? 8 : 0)) * 2);
            unsigned a_h[4], a_l[4];
            ldm4(a_h, sbase + SM_AH + aoff);
            ldm4(a_l, sbase + SM_AL + aoff);
#pragma unroll
            for (int j = 0; j < 16; j++) {
                uint4 B = bsm[(k16 * 16 + j) * 32 + lane];
                mma_bf16(acc[j], a_h, B.x, B.y);
                mma_bf16(acc[j], a_l, B.x, B.y);
                mma_bf16(acc[j], a_h, B.z, B.w);
            }
        }
    }

    // ---- LN stats finalize (tid pairs share a row) ----
    ssum += __shfl_xor_sync(0xffffffffu, ssum, 1);
    ssq  += __shfl_xor_sync(0xffffffffu, ssq, 1);
    if ((tid & 1) == 0) {
        float mu = ssum * (1.f / DD);
        float var = ssq * (1.f / DD) - mu * mu;
        mu_s[row] = mu;
        inv_s[row] = rsqrtf(var + 1e-5f);
    }
    __syncthreads();

    // ---- epilogue: LN fold + wkv -> smem (overlay A region, pitch 68) ----
    float* wkv_s = reinterpret_cast<float*>(smc);
    int tr = lane >> 2, tc = lane & 3;
#pragma unroll
    for (int j = 0; j < 16; j++) {
        int n = j * 4 + tc;
        int o0 = 2 * n;
        float etf = etf_s[n];
        float wsk = ws_s[o0], wsv = ws_s[o0 + 1];
        float lbk = lb_s[o0], lbv = lb_s[o0 + 1];
#pragma unroll
        for (int h = 0; h < 2; h++) {
            int r = R0 + tr + h * 8;
            float mu = mu_s[r], inv = inv_s[r];
            float k = inv * (acc[j][2 * h] - mu * wsk) + lbk;
            float v = inv * (acc[j][2 * h + 1] - mu * wsv) + lbv;
            wkv_s[r * 68 + n] = expf(-etf * k) * v;
        }
    }
    __syncthreads();

    // ---- coalesced g_wkv store ----
    {
        int rr = tid >> 1;
        int seg = tid & 1;
        float* dst = &g_wkv[((size_t)(b * SS) + t0 + rr) * NN + seg * 32];
        const float* src = &wkv_s[rr * 68 + seg * 32];
#pragma unroll
        for (int k4 = 0; k4 < 8; k4++)
            reinterpret_cast<float4*>(dst)[k4] = *reinterpret_cast<const float4*>(src + 4 * k4);
    }
    // ---- chunk sums (4 sub-chunks of 32 rows) ----
    {
        int sub = tid >> 6;
        int n = tid & 63;
        float w = g_w[n];
        float a = 0.f;
#pragma unroll
        for (int r2 = 0; r2 < 32; r2++) a = a * w + wkv_s[(sub * 32 + r2) * 68 + n];
        g_chunk[((size_t)b * NCH + tp * 4 + sub) * NN + n] = a;
    }
}

// ---------------- carry prefix over chunks ----------------
__global__ void scan_carry(const float* __restrict__ td, float* __restrict__ lastout,
                           int write_last) {
    int tid = threadIdx.x;
    int n = tid & (NN - 1);
    int b = tid >> 6;
    float wL = expf((float)CHL * td[n]);
    float carry = 0.f;
    for (int c0 = 0; c0 < NCH; c0 += 8) {
        float v[8];
#pragma unroll
        for (int i = 0; i < 8; i++) v[i] = g_chunk[((size_t)b * NCH + c0 + i) * NN + n];
#pragma unroll
        for (int i = 0; i < 8; i++) {
            g_carry[((size_t)b * NCH + c0 + i) * NN + n] = carry;
            carry = carry * wL + v[i];
        }
    }
    if (write_last) lastout[b * NN + n] = carry;
}

// ---------------- kernel C: fused scan + output projection ----------------
#define SPITCH 36
__global__ void __launch_bounds__(1024, 1)
kernelC(float* __restrict__ out) {
    __shared__ float wk[TILE_C * NN];
    __shared__ float sT[NN * SPITCH];

    int b = blockIdx.x >> 7;
    int c = blockIdx.x & 127;
    int t0 = c * TILE_C;
    int tid = threadIdx.x;
    int wg = tid >> 9;
    int dtid = tid & 511;

    if (tid < 512)
        reinterpret_cast<float4*>(wk)[tid] =
            reinterpret_cast<const float4*>(&g_wkv[((size_t)(b * SS) + t0) * NN])[tid];
    __syncthreads();

    if (tid < NN) {
        int n = tid;
        float w = g_w[n];
        float st = g_carry[((size_t)b * NCH + c) * NN + n];
#pragma unroll
        for (int r = 0; r < TILE_C; r++) {
            st = st * w + wk[r * NN + n];
            sT[n * SPITCH + r] = st;
        }
    }
    __syncthreads();

    float2 acc[8][2];
#pragma unroll
    for (int p = 0; p < 8; p++) { acc[p][0] = make_float2(0.f, 0.f); acc[p][1] = make_float2(0.f, 0.f); }

    const float* sBase = &sT[wg * 16];
#pragma unroll 2
    for (int n4 = 0; n4 < 16; n4++) {
        float4 wA = __ldg(&g_owQ[n4 * 1024 + dtid]);
        float4 wB = __ldg(&g_owQ[n4 * 1024 + 512 + dtid]);
#pragma unroll
        for (int j = 0; j < 4; j++) {
            int n = 4 * n4 + j;
            float wa = (j == 0) ? wA.x : (j == 1) ? wA.y : (j == 2) ? wA.z : wA.w;
            float wb2v = (j == 0) ? wB.x : (j == 1) ? wB.y : (j == 2) ? wB.z : wB.w;
            float2 wa2 = make_float2(wa, wa);
            float2 wb2 = make_float2(wb2v, wb2v);
            const float* sb = sBase + n * SPITCH;
#pragma unroll
            for (int qq = 0; qq < 4; qq++) {
                float4 s4 = *reinterpret_cast<const float4*>(sb + 4 * qq);
                float2 slo = make_float2(s4.x, s4.y);
                float2 shi = make_float2(s4.z, s4.w);
                acc[2 * qq][0]     = ffma2(slo, wa2, acc[2 * qq][0]);
                acc[2 * qq][1]     = ffma2(slo, wb2, acc[2 * qq][1]);
                acc[2 * qq + 1][0] = ffma2(shi, wa2, acc[2 * qq + 1][0]);
                acc[2 * qq + 1][1] = ffma2(shi, wb2, acc[2 * qq + 1][1]);
            }
        }
    }

    float* ob = out + ((size_t)(b * SS) + t0 + wg * 16) * DD;
#pragma unroll
    for (int p = 0; p < 8; p++) {
        ob[(size_t)(2 * p) * DD + dtid]           = acc[p][0].x;
        ob[(size_t)(2 * p + 1) * DD + dtid]       = acc[p][0].y;
        ob[(size_t)(2 * p) * DD + 512 + dtid]     = acc[p][1].x;
        ob[(size_t)(2 * p + 1) * DD + 512 + dtid] = acc[p][1].y;
    }
}

// ---------------- launch ----------------
extern "C" void kernel_launch(void* const* d_in, const int* in_sizes, int n_in,
                              void* d_out, int out_size) {
    const float* x   = (const float*)d_in[0];
    const float* td  = (const float*)d_in[1];
    const float* tf  = (const float*)d_in[2];
    const float* kw  = (const float*)d_in[3];
    const float* vw  = (const float*)d_in[4];
    const float* ow  = (const float*)d_in[5];
    const float* tsg = (const float*)d_in[6];
    const float* lnw = (const float*)d_in[7];
    const float* lnb = (const float*)d_in[8];
    float* out = (float*)d_out;

    cudaFuncSetAttribute(kernelA, cudaFuncAttributeMaxDynamicSharedMemorySize, SMEM_A_BYTES);

    prep_a<<<(DD * 128) / 256, 256>>>(kw, vw, lnw, tsg, td, tf);
    prep_bfrag<<<128, 256>>>();
    prep_ow<<<64, 256>>>(ow);
    prep_b<<<128, 256>>>(kw, vw, lnb);
    kernelA<<<BB * 32, 256, SMEM_A_BYTES>>>(x);
    int write_last = (out_size >= BB * SS * DD + BB * NN) ? 1 : 0;
    scan_carry<<<1, 512>>>(td, out + (size_t)BB * SS * DD, write_last);
    kernelC<<<BB * (SS / TILE_C), 1024>>>(out);
}

// round 13
// speedup vs baseline: 1.8705x; 1.0869x over previous
#include <cuda_runtime.h>
#include <cuda_fp16.h>
#include <cstdint>
#include <math.h>

#define BB 8
#define SS 4096
#define DD 1024
#define NN 64
#define SHIFT 2048
#define NCH 128
#define CHL 32
#define TILE_C 32

// ---------------- scratch (device globals) ----------------
__device__ float g_wT[DD * 128];            // [d][o]: o=2n -> lnw*kw, o=2n+1 -> lnw*vw
__device__ float g_wsum[128];
__device__ float g_lbsum[128];
__device__ float g_gate[DD];
__device__ float g_w[NN];                   // exp(time_decay)
__device__ float g_exptf[NN];               // exp(time_first)
__device__ float4 g_owQ[16 * DD];           // [n4][d] = ow[d][4n4..4n4+3]
__device__ uint2 g_bfragH[16 * 2048];       // frag-major fp16 weights: [ch][s][n8][lane] = (b0,b1)
__device__ float g_wkv[BB * SS * NN];
__device__ float g_chunk[BB * NCH * NN];
__device__ float g_carry[BB * NCH * NN];

// ---------------- packed fp32x2 FMA ----------------
__device__ __forceinline__ float2 ffma2(float2 a, float2 b, float2 c) {
    float2 d;
    asm("fma.rn.f32x2 %0, %1, %2, %3;"
        : "=l"(*reinterpret_cast<unsigned long long*>(&d))
        : "l"(*reinterpret_cast<unsigned long long*>(&a)),
          "l"(*reinterpret_cast<unsigned long long*>(&b)),
          "l"(*reinterpret_cast<unsigned long long*>(&c)));
    return d;
}

// ---------------- HMMA helpers (sm_80+ baseline) ----------------
__device__ __forceinline__ void mma_f16(float* c, const unsigned* a, unsigned b0, unsigned b1) {
    asm volatile("mma.sync.aligned.m16n8k16.row.col.f32.f16.f16.f32 "
                 "{%0,%1,%2,%3}, {%4,%5,%6,%7}, {%8,%9}, {%0,%1,%2,%3};"
                 : "+f"(c[0]), "+f"(c[1]), "+f"(c[2]), "+f"(c[3])
                 : "r"(a[0]), "r"(a[1]), "r"(a[2]), "r"(a[3]), "r"(b0), "r"(b1));
}
__device__ __forceinline__ void ldm4(unsigned* r, unsigned addr) {
    asm volatile("ldmatrix.sync.aligned.m8n8.x4.shared.b16 {%0,%1,%2,%3}, [%4];"
                 : "=r"(r[0]), "=r"(r[1]), "=r"(r[2]), "=r"(r[3]) : "r"(addr));
}
__device__ __forceinline__ unsigned packh(float a, float b) {
    __half2 t = __floats2half2_rn(a, b);
    return *reinterpret_cast<unsigned*>(&t);
}
__device__ __forceinline__ float h2f(float a) {
    return __half2float(__float2half_rn(a));
}

// ---------------- prep kernels ----------------
__global__ void prep_a(const float* __restrict__ kw, const float* __restrict__ vw,
                       const float* __restrict__ lnw, const float* __restrict__ tsg,
                       const float* __restrict__ td, const float* __restrict__ tf) {
    int idx = blockIdx.x * 256 + threadIdx.x;
    int d = idx >> 7;
    int o = idx & 127;
    int n = o >> 1;
    const float* src = (o & 1) ? vw : kw;
    g_wT[idx] = lnw[d] * src[n * DD + d];
    if (o == 0) g_gate[d] = 1.f / (1.f + expf(-tsg[d]));
    if (idx < NN) g_w[idx] = expf(td[idx]);
    else if (idx < 2 * NN) g_exptf[idx - NN] = expf(tf[idx - NN]);
}

// fp16 fragment-major weight pack + ow transpose (merged: keeps launch count at 6)
__global__ void prep_bfrag(const float* __restrict__ ow) {
    int idx = blockIdx.x * 256 + threadIdx.x;   // 0..32767
    int lane = idx & 31;
    int n8 = (idx >> 5) & 15;
    int s = (idx >> 9) & 3;
    int ch = idx >> 11;
    int o = n8 * 8 + (lane >> 2);
    int kb = ch * 64 + s * 16 + (lane & 3) * 2;
    float w0 = g_wT[(size_t)kb * 128 + o];
    float w1 = g_wT[(size_t)(kb + 1) * 128 + o];
    float w8 = g_wT[(size_t)(kb + 8) * 128 + o];
    float w9 = g_wT[(size_t)(kb + 9) * 128 + o];
    g_bfragH[idx] = make_uint2(packh(w0, w1), packh(w8, w9));
    if (idx < 16384) {
        int d = idx & (DD - 1);
        int n4 = idx >> 10;
        g_owQ[idx] = *reinterpret_cast<const float4*>(&ow[d * NN + 4 * n4]);
    }
}

__global__ void prep_b(const float* __restrict__ kw, const float* __restrict__ vw,
                       const float* __restrict__ lnb) {
    __shared__ float red[2][8];
    int o = blockIdx.x;
    int n = o >> 1;
    const float* src = (o & 1) ? vw : kw;
    int tid = threadIdx.x;
    float ws = 0.f, lb = 0.f;
    for (int d = tid; d < DD; d += 256) {
        ws += g_wT[d * 128 + o];
        lb += lnb[d] * src[n * DD + d];
    }
#pragma unroll
    for (int off = 16; off; off >>= 1) {
        ws += __shfl_xor_sync(0xffffffffu, ws, off);
        lb += __shfl_xor_sync(0xffffffffu, lb, off);
    }
    if ((tid & 31) == 0) { red[0][tid >> 5] = ws; red[1][tid >> 5] = lb; }
    __syncthreads();
    if (tid == 0) {
        float a = 0.f, c = 0.f;
#pragma unroll
        for (int i = 0; i < 8; i++) { a += red[0][i]; c += red[1][i]; }
        g_wsum[o] = a;
        g_lbsum[o] = c;
    }
}

// ---------------- kernel A: HMMA fp16-split KV projection ----------------
// grid 256 (8 b x 32 tiles of 128 rows), 256 threads, occ 2.
// smem: Ah 0..18432 | Al 18432..36864 | B 36864..53248 | consts to 55552
#define SM_AH 0
#define SM_AL 18432
#define SM_BS 36864
#define SM_MU 53248
#define SM_INV 53760
#define SM_WS 54272
#define SM_LB 54784
#define SM_ETF 55296
#define SMEM_A_BYTES 55552

__global__ void __launch_bounds__(256, 2)
kernelA(const float* __restrict__ x) {
    extern __shared__ char smc[];
    unsigned sbase = (unsigned)__cvta_generic_to_shared(smc);

    int b = blockIdx.x >> 5;
    int tp = blockIdx.x & 31;
    int t0 = tp * 128;
    int tid = threadIdx.x;
    int lane = tid & 31;
    int warp = tid >> 5;
    int row = tid >> 1;                 // staging row 0..127
    int khalf = (tid & 1) * 32;         // float offset within 64-d chunk

    float* mu_s  = reinterpret_cast<float*>(smc + SM_MU);
    float* inv_s = reinterpret_cast<float*>(smc + SM_INV);
    float* ws_s  = reinterpret_cast<float*>(smc + SM_WS);
    float* lb_s  = reinterpret_cast<float*>(smc + SM_LB);
    float* etf_s = reinterpret_cast<float*>(smc + SM_ETF);
    if (tid < 128) {
        ws_s[tid] = g_wsum[tid];
        lb_s[tid] = g_lbsum[tid];
        if (tid < 64) etf_s[tid] = g_exptf[tid];
    }

    const float4* xt4 = reinterpret_cast<const float4*>(x + ((size_t)(b * SS) + t0 + row) * DD);
    const float4* xc4 = reinterpret_cast<const float4*>(x + ((size_t)(b * SS) + ((t0 + row) ^ SHIFT)) * DD);
    const float4* g4 = reinterpret_cast<const float4*>(g_gate);

    float ssum = 0.f, ssq = 0.f;
    float acc[16][4];
#pragma unroll
    for (int j = 0; j < 16; j++)
#pragma unroll
        for (int c = 0; c < 4; c++) acc[j][c] = 0.f;

    char* ah = smc + SM_AH;
    char* al = smc + SM_AL;
    const uint2* bsm = reinterpret_cast<const uint2*>(smc + SM_BS);
    int R0 = warp * 16;

#pragma unroll 1
    for (int ch = 0; ch < 16; ch++) {
        __syncthreads();   // previous compute done; safe to overwrite tiles
        // ---- stage A: blend + stats + fp16 hi/lo split ----
#pragma unroll
        for (int i = 0; i < 8; i++) {
            int f4i = ch * 16 + (tid & 1) * 8 + i;
            float4 xv = xt4[f4i];
            float4 xc = xc4[f4i];
            float4 g = __ldg(&g4[f4i]);
            float s0 = xv.x + g.x * (xc.x - xv.x);
            float s1 = xv.y + g.y * (xc.y - xv.y);
            float s2 = xv.z + g.z * (xc.z - xv.z);
            float s3 = xv.w + g.w * (xc.w - xv.w);
            ssum += s0 + s1 + s2 + s3;
            ssq  += s0 * s0 + s1 * s1 + s2 * s2 + s3 * s3;
            float h0 = h2f(s0), h1 = h2f(s1), h2 = h2f(s2), h3 = h2f(s3);
            int klocal = khalf + i * 4;
            *reinterpret_cast<uint2*>(ah + row * 144 + klocal * 2) =
                make_uint2(packh(h0, h1), packh(h2, h3));
            *reinterpret_cast<uint2*>(al + row * 144 + klocal * 2) =
                make_uint2(packh(s0 - h0, s1 - h1), packh(s2 - h2, s3 - h3));
        }
        // ---- stage B fragments (linear 16 KB copy) ----
        {
            const uint4* bsrc = reinterpret_cast<const uint4*>(&g_bfragH[ch * 2048]);
            uint4* bdst = reinterpret_cast<uint4*>(smc + SM_BS);
#pragma unroll
            for (int q = 0; q < 4; q++) bdst[q * 256 + tid] = bsrc[q * 256 + tid];
        }
        __syncthreads();

        // ---- compute: 4 k16 steps x 16 n8 tiles x 2 split-MMAs ----
#pragma unroll
        for (int k16 = 0; k16 < 4; k16++) {
            unsigned aoff = (unsigned)((R0 + (lane & 15)) * 144 + (k16 * 16 + ((lane & 16) ? 8 : 0)) * 2);
            unsigned a_h[4], a_l[4];
            ldm4(a_h, sbase + SM_AH + aoff);
            ldm4(a_l, sbase + SM_AL + aoff);
#pragma unroll
            for (int j = 0; j < 16; j++) {
                uint2 B = bsm[(k16 * 16 + j) * 32 + lane];
                mma_f16(acc[j], a_h, B.x, B.y);
                mma_f16(acc[j], a_l, B.x, B.y);
            }
        }
    }

    // ---- LN stats finalize (tid pairs share a row) ----
    ssum += __shfl_xor_sync(0xffffffffu, ssum, 1);
    ssq  += __shfl_xor_sync(0xffffffffu, ssq, 1);
    if ((tid & 1) == 0) {
        float mu = ssum * (1.f / DD);
        float var = ssq * (1.f / DD) - mu * mu;
        mu_s[row] = mu;
        inv_s[row] = rsqrtf(var + 1e-5f);
    }
    __syncthreads();

    // ---- epilogue: LN fold + wkv -> smem (overlay A region, pitch 68) ----
    float* wkv_s = reinterpret_cast<float*>(smc);
    int tr = lane >> 2, tc = lane & 3;
#pragma unroll
    for (int j = 0; j < 16; j++) {
        int n = j * 4 + tc;
        int o0 = 2 * n;
        float etf = etf_s[n];
        float wsk = ws_s[o0], wsv = ws_s[o0 + 1];
        float lbk = lb_s[o0], lbv = lb_s[o0 + 1];
#pragma unroll
        for (int h = 0; h < 2; h++) {
            int r = R0 + tr + h * 8;
            float mu = mu_s[r], inv = inv_s[r];
            float k = inv * (acc[j][2 * h] - mu * wsk) + lbk;
            float v = inv * (acc[j][2 * h + 1] - mu * wsv) + lbv;
            wkv_s[r * 68 + n] = expf(-etf * k) * v;
        }
    }
    __syncthreads();

    // ---- coalesced g_wkv store ----
    {
        int rr = tid >> 1;
        int seg = tid & 1;
        float* dst = &g_wkv[((size_t)(b * SS) + t0 + rr) * NN + seg * 32];
        const float* src = &wkv_s[rr * 68 + seg * 32];
#pragma unroll
        for (int k4 = 0; k4 < 8; k4++)
            reinterpret_cast<float4*>(dst)[k4] = *reinterpret_cast<const float4*>(src + 4 * k4);
    }
    // ---- chunk sums (4 sub-chunks of 32 rows) ----
    {
        int sub = tid >> 6;
        int n = tid & 63;
        float w = g_w[n];
        float a = 0.f;
#pragma unroll
        for (int r2 = 0; r2 < 32; r2++) a = a * w + wkv_s[(sub * 32 + r2) * 68 + n];
        g_chunk[((size_t)b * NCH + tp * 4 + sub) * NN + n] = a;
    }
}

// ---------------- carry prefix over chunks ----------------
__global__ void scan_carry(const float* __restrict__ td, float* __restrict__ lastout,
                           int write_last) {
    int tid = threadIdx.x;
    int n = tid & (NN - 1);
    int b = tid >> 6;
    float wL = expf((float)CHL * td[n]);
    float carry = 0.f;
    for (int c0 = 0; c0 < NCH; c0 += 8) {
        float v[8];
#pragma unroll
        for (int i = 0; i < 8; i++) v[i] = g_chunk[((size_t)b * NCH + c0 + i) * NN + n];
#pragma unroll
        for (int i = 0; i < 8; i++) {
            g_carry[((size_t)b * NCH + c0 + i) * NN + n] = carry;
            carry = carry * wL + v[i];
        }
    }
    if (write_last) lastout[b * NN + n] = carry;
}

// ---------------- kernel C: fused scan + output projection ----------------
#define SPITCH 36
__global__ void __launch_bounds__(1024, 1)
kernelC(float* __restrict__ out) {
    __shared__ float wk[TILE_C * NN];
    __shared__ float sT[NN * SPITCH];

    int b = blockIdx.x >> 7;
    int c = blockIdx.x & 127;
    int t0 = c * TILE_C;
    int tid = threadIdx.x;
    int wg = tid >> 9;
    int dtid = tid & 511;

    if (tid < 512)
        reinterpret_cast<float4*>(wk)[tid] =
            reinterpret_cast<const float4*>(&g_wkv[((size_t)(b * SS) + t0) * NN])[tid];
    __syncthreads();

    if (tid < NN) {
        int n = tid;
        float w = g_w[n];
        float st = g_carry[((size_t)b * NCH + c) * NN + n];
#pragma unroll
        for (int r = 0; r < TILE_C; r++) {
            st = st * w + wk[r * NN + n];
            sT[n * SPITCH + r] = st;
        }
    }
    __syncthreads();

    float2 acc[8][2];
#pragma unroll
    for (int p = 0; p < 8; p++) { acc[p][0] = make_float2(0.f, 0.f); acc[p][1] = make_float2(0.f, 0.f); }

    const float* sBase = &sT[wg * 16];
#pragma unroll 2
    for (int n4 = 0; n4 < 16; n4++) {
        float4 wA = __ldg(&g_owQ[n4 * 1024 + dtid]);
        float4 wB = __ldg(&g_owQ[n4 * 1024 + 512 + dtid]);
#pragma unroll
        for (int j = 0; j < 4; j++) {
            int n = 4 * n4 + j;
            float wa = (j == 0) ? wA.x : (j == 1) ? wA.y : (j == 2) ? wA.z : wA.w;
            float wb2v = (j == 0) ? wB.x : (j == 1) ? wB.y : (j == 2) ? wB.z : wB.w;
            float2 wa2 = make_float2(wa, wa);
            float2 wb2 = make_float2(wb2v, wb2v);
            const float* sb = sBase + n * SPITCH;
#pragma unroll
            for (int qq = 0; qq < 4; qq++) {
                float4 s4 = *reinterpret_cast<const float4*>(sb + 4 * qq);
                float2 slo = make_float2(s4.x, s4.y);
                float2 shi = make_float2(s4.z, s4.w);
                acc[2 * qq][0]     = ffma2(slo, wa2, acc[2 * qq][0]);
                acc[2 * qq][1]     = ffma2(slo, wb2, acc[2 * qq][1]);
                acc[2 * qq + 1][0] = ffma2(shi, wa2, acc[2 * qq + 1][0]);
                acc[2 * qq + 1][1] = ffma2(shi, wb2, acc[2 * qq + 1][1]);
            }
        }
    }

    float* ob = out + ((size_t)(b * SS) + t0 + wg * 16) * DD;
#pragma unroll
    for (int p = 0; p < 8; p++) {
        ob[(size_t)(2 * p) * DD + dtid]           = acc[p][0].x;
        ob[(size_t)(2 * p + 1) * DD + dtid]       = acc[p][0].y;
        ob[(size_t)(2 * p) * DD + 512 + dtid]     = acc[p][1].x;
        ob[(size_t)(2 * p + 1) * DD + 512 + dtid] = acc[p][1].y;
    }
}

// ---------------- launch ----------------
extern "C" void kernel_launch(void* const* d_in, const int* in_sizes, int n_in,
                              void* d_out, int out_size) {
    const float* x   = (const float*)d_in[0];
    const float* td  = (const float*)d_in[1];
    const float* tf  = (const float*)d_in[2];
    const float* kw  = (const float*)d_in[3];
    const float* vw  = (const float*)d_in[4];
    const float* ow  = (const float*)d_in[5];
    const float* tsg = (const float*)d_in[6];
    const float* lnw = (const float*)d_in[7];
    const float* lnb = (const float*)d_in[8];
    float* out = (float*)d_out;

    cudaFuncSetAttribute(kernelA, cudaFuncAttributeMaxDynamicSharedMemorySize, SMEM_A_BYTES);

    prep_a<<<(DD * 128) / 256, 256>>>(kw, vw, lnw, tsg, td, tf);
    prep_bfrag<<<128, 256>>>(ow);
    prep_b<<<128, 256>>>(kw, vw, lnb);
    kernelA<<<BB * 32, 256, SMEM_A_BYTES>>>(x);
    int write_last = (out_size >= BB * SS * DD + BB * NN) ? 1 : 0;
    scan_carry<<<1, 512>>>(td, out + (size_t)BB * SS * DD, write_last);
    kernelC<<<BB * (SS / TILE_C), 1024>>>(out);
}